// round 15
// baseline (speedup 1.0000x reference)
#include <cuda_runtime.h>
#include <cuda_fp16.h>
#include <math.h>
#include <stdint.h>

// Problem constants
#define BB 8
#define NN 1024
#define DD 768
#define HH 4
#define MM (BB * NN)
#define ALPHA_LRELU 0.2f

// ----------------------------------------------------------------------------
// Scratch. GEMM operands live as SWIZZLED PANELS:
//   panel block: [blk128][kchunk][128 rows x 32 halves] = 8KB
//   in-block byte addr = pan(row*64 + (k%32)*2), pan(x) = x ^ ((x>>3)&0x30)
// ----------------------------------------------------------------------------
__device__ __align__(256) __half g_X16[(long)MM * DD];              // A-panel K=768
__device__ __align__(256) __half g_W16T[(long)HH * DD * DD];        // B-panel K=768 per head
__device__ __align__(256) __half g_Wo16T[(long)DD * HH * DD];       // B-panel K=3072
__device__ __align__(256) __half g_Wh16[(long)HH * MM * DD];        // row-major (fvec)
__device__ __align__(256) __half g_WhT16[(long)HH * BB * DD * NN];  // B-panel K=1024 per (h,b)
__device__ __align__(256) __half g_xx16[(long)MM * (HH * DD)];      // A-panel K=3072
__device__ __align__(256) __half g_Who16[(long)MM * DD];            // row-major (fvec)
__device__ __align__(256) __half g_WhoT16[(long)BB * DD * NN];      // B-panel K=1024 per b
__device__ __align__(256) __half g_P16[(long)HH * BB * NN * NN];    // A-panel K=1024 per (h,b)
__device__ float g_f1[HH * MM];
__device__ float g_f2[HH * MM];
__device__ float g_f1o[MM];
__device__ float g_f2o[MM];

// ----------------------------------------------------------------------------
// helpers
// ----------------------------------------------------------------------------
__device__ __forceinline__ uint32_t smem_u32(const void* p) {
    uint32_t a;
    asm("{ .reg .u64 t; cvta.to.shared.u64 t, %1; cvt.u32.u64 %0, t; }" : "=r"(a) : "l"(p));
    return a;
}
__device__ __host__ __forceinline__ uint32_t pan(uint32_t x) {
    return x ^ ((x >> 3) & 0x30);
}
__device__ __forceinline__ void ldsm_x4(uint32_t& r0, uint32_t& r1, uint32_t& r2, uint32_t& r3,
                                        uint32_t addr) {
    asm volatile("ldmatrix.sync.aligned.m8n8.x4.shared.b16 {%0,%1,%2,%3}, [%4];"
                 : "=r"(r0), "=r"(r1), "=r"(r2), "=r"(r3) : "r"(addr));
}

#define MBAR_INIT(addr, cnt) \
    asm volatile("mbarrier.init.shared.b64 [%0], %1;" :: "r"(addr), "r"(cnt) : "memory")
#define MBAR_EXPECT(addr, bytes) \
    asm volatile("mbarrier.arrive.expect_tx.shared.b64 _, [%0], %1;" :: "r"(addr), "r"(bytes) : "memory")
#define MBAR_ARRIVE(addr) \
    asm volatile("mbarrier.arrive.shared.b64 _, [%0];" :: "r"(addr) : "memory")
#define MBAR_WAIT(addr, par) do { \
    asm volatile("{\n\t.reg .pred P1;\n\tWL_%=:\n\t" \
        "mbarrier.try_wait.parity.shared.b64 P1, [%0], %1;\n\t" \
        "@P1 bra.uni WD_%=;\n\tbra.uni WL_%=;\n\tWD_%=:\n\t}" \
        :: "r"(addr), "r"(par) : "memory"); \
} while (0)
#define BULK_G2S(dst, src, bytes, mbar) \
    asm volatile("cp.async.bulk.shared::cluster.global.mbarrier::complete_tx::bytes [%0], [%1], %2, [%3];" \
        :: "r"(dst), "l"(src), "r"(bytes), "r"(mbar) : "memory")

// ----------------------------------------------------------------------------
// fp16 mma.sync GEMM over swizzled panels.
// 128x128 CTA tile, 256 threads (8 warps, warp 32x64), KT=32, 6-stage
// cp.async.bulk pipeline, full/empty mbarriers, 2 CTAs/SM, warp start stagger.
// EPI: 1 = elu -> half A-PANEL out, 2 = elu + residual -> f32 row-major,
//      5 = plain -> half row-major AND half transposed B-panel (R = panel base)
// ----------------------------------------------------------------------------
#define KT 32
#define STAGES 6
#define ABLK 8192
#define BBLK 8192
#define STAGEB (ABLK + BBLK)                  // 16384
#define GEMM_SMEM (STAGES * STAGEB + 128)     // 98432 -> 2 CTAs/SM

template <int EPI>
__global__ void __launch_bounds__(256, 2)
hgemm(const __half* __restrict__ A, const __half* __restrict__ B,
      void* __restrict__ Cv, const float* __restrict__ R,
      int K, int ldc, long sA, long sB, long sC, long sC2, int zmod, long sR)
{
    extern __shared__ char smc[];
    uint32_t sb = smem_u32(smc);
    uint32_t fullb = sb + STAGES * STAGEB;
    uint32_t emptyb = fullb + 64;
    int tid = threadIdx.x;
    int l = tid & 31;
    int w = tid >> 5;

    int z = blockIdx.z;
    const char* Ag = (const char*)(A + (long)z * sA);
    const char* Bg = (const char*)(B + (long)z * sB);
    const float* Rb = (EPI == 2) ? (R + (long)z * sR) : nullptr;

    int brow = blockIdx.y * 128;
    int bcol = blockIdx.x * 128;
    int m0 = (w & 3) * 32;
    int n0 = (w >> 2) * 64;

    float c[2][8][4];
    #pragma unroll
    for (int i = 0; i < 2; i++)
        #pragma unroll
        for (int j = 0; j < 8; j++)
            #pragma unroll
            for (int q = 0; q < 4; q++) c[i][j][q] = 0.0f;

    int nk = K / KT;

    if (tid == 0) {
        #pragma unroll
        for (int b = 0; b < STAGES; b++) {
            MBAR_INIT(fullb + b * 8, 1);
            MBAR_INIT(emptyb + b * 8, 8);
        }
    }
    __syncthreads();

    auto issue = [&](int s) {
        int buf = s % STAGES;
        MBAR_WAIT(emptyb + buf * 8, (uint32_t)(((s / STAGES) + 1) & 1));
        uint32_t dst = sb + buf * STAGEB;
        uint32_t bar = fullb + buf * 8;
        const char* srcA = Ag + ((long)blockIdx.y * (K >> 5) + s) * ABLK;
        const char* srcB = Bg + ((long)blockIdx.x * (K >> 5) + s) * BBLK;
        asm volatile("fence.proxy.async.shared::cta;" ::: "memory");
        MBAR_EXPECT(bar, STAGEB);
        BULK_G2S(dst, srcA, ABLK, bar);
        BULK_G2S(dst + ABLK, srcB, BBLK, bar);
    };

    if (tid == 0) {
        for (int pf = 0; pf < STAGES - 1 && pf < nk; pf++) issue(pf);
    }

    // per-warp start stagger (~48*w cycles)
    {
        float dly = 1.0f + (float)l * 1e-30f;
        int iters = w * 12;
        for (int i = 0; i < iters; i++)
            dly = fmaf(dly, 1.0000001f, 1e-30f);
        if (dly == 1234.5f) ((volatile float*)Cv)[0] = dly;   // never true
    }

    uint32_t aof[2][2], bof[4][2];
    #pragma unroll
    for (int mi = 0; mi < 2; mi++)
        #pragma unroll
        for (int ks = 0; ks < 2; ks++)
            aof[mi][ks] = pan((uint32_t)(m0 + mi * 16 + (l & 15)) * 64 +
                              (uint32_t)ks * 32 + (uint32_t)(l >> 4) * 16);
    #pragma unroll
    for (int np = 0; np < 4; np++)
        #pragma unroll
        for (int ks = 0; ks < 2; ks++)
            bof[np][ks] = pan((uint32_t)(n0 + np * 16 + (l & 15)) * 64 +
                              (uint32_t)ks * 32 + (uint32_t)(l >> 4) * 16);

    for (int s = 0; s < nk; s++) {
        int buf = s % STAGES;
        MBAR_WAIT(fullb + buf * 8, (uint32_t)((s / STAGES) & 1));

        uint32_t tA = sb + buf * STAGEB;
        uint32_t tB = tA + ABLK;

        // ks = 0
        {
            uint32_t a[2][4], b[4][4];
            #pragma unroll
            for (int mi = 0; mi < 2; mi++)
                ldsm_x4(a[mi][0], a[mi][1], a[mi][2], a[mi][3], tA + aof[mi][0]);
            #pragma unroll
            for (int np = 0; np < 4; np++)
                ldsm_x4(b[np][0], b[np][1], b[np][2], b[np][3], tB + bof[np][0]);
            #pragma unroll
            for (int mi = 0; mi < 2; mi++)
                #pragma unroll
                for (int nf = 0; nf < 8; nf++) {
                    uint32_t b0 = b[nf >> 1][(nf & 1) + 0];
                    uint32_t b1 = b[nf >> 1][(nf & 1) + 2];
                    asm volatile(
                        "mma.sync.aligned.m16n8k16.row.col.f32.f16.f16.f32 "
                        "{%0,%1,%2,%3}, {%4,%5,%6,%7}, {%8,%9}, {%0,%1,%2,%3};"
                        : "+f"(c[mi][nf][0]), "+f"(c[mi][nf][1]),
                          "+f"(c[mi][nf][2]), "+f"(c[mi][nf][3])
                        : "r"(a[mi][0]), "r"(a[mi][1]), "r"(a[mi][2]), "r"(a[mi][3]),
                          "r"(b0), "r"(b1));
                }
        }
        // ks = 1
        {
            uint32_t a[2][4], b[4][4];
            #pragma unroll
            for (int mi = 0; mi < 2; mi++)
                ldsm_x4(a[mi][0], a[mi][1], a[mi][2], a[mi][3], tA + aof[mi][1]);
            #pragma unroll
            for (int np = 0; np < 4; np++)
                ldsm_x4(b[np][0], b[np][1], b[np][2], b[np][3], tB + bof[np][1]);
            if (l == 0) MBAR_ARRIVE(emptyb + buf * 8);
            if (tid == 0 && s + STAGES - 1 < nk) issue(s + STAGES - 1);
            #pragma unroll
            for (int mi = 0; mi < 2; mi++)
                #pragma unroll
                for (int nf = 0; nf < 8; nf++) {
                    uint32_t b0 = b[nf >> 1][(nf & 1) + 0];
                    uint32_t b1 = b[nf >> 1][(nf & 1) + 2];
                    asm volatile(
                        "mma.sync.aligned.m16n8k16.row.col.f32.f16.f16.f32 "
                        "{%0,%1,%2,%3}, {%4,%5,%6,%7}, {%8,%9}, {%0,%1,%2,%3};"
                        : "+f"(c[mi][nf][0]), "+f"(c[mi][nf][1]),
                          "+f"(c[mi][nf][2]), "+f"(c[mi][nf][3])
                        : "r"(a[mi][0]), "r"(a[mi][1]), "r"(a[mi][2]), "r"(a[mi][3]),
                          "r"(b0), "r"(b1));
                }
        }
    }

    // epilogue
    long coff = (long)(z % zmod) * sC + (long)(z / zmod) * sC2;
    #pragma unroll
    for (int mi = 0; mi < 2; mi++) {
        #pragma unroll
        for (int hh = 0; hh < 2; hh++) {
            long rg = brow + m0 + mi * 16 + (l >> 2) + hh * 8;
            #pragma unroll
            for (int nf = 0; nf < 8; nf++) {
                float v0 = c[mi][nf][hh * 2 + 0];
                float v1 = c[mi][nf][hh * 2 + 1];
                if (EPI == 1 || EPI == 2) {
                    v0 = (v0 > 0.0f) ? v0 : expm1f(v0);
                    v1 = (v1 > 0.0f) ? v1 : expm1f(v1);
                }
                long colg = bcol + n0 + nf * 8 + (l & 3) * 2;
                if (EPI == 1) {
                    long mg = (long)(z % zmod) * sC + rg;
                    long kg = (long)(z / zmod) * sC2 + colg;
                    long ba = ((mg >> 7) * (ldc >> 5) + (kg >> 5)) * 8192L +
                              pan((uint32_t)((mg & 127) * 64 + (kg & 31) * 2));
                    *(__half2*)((char*)Cv + ba) = __floats2half2_rn(v0, v1);
                } else if (EPI == 5) {
                    long ci = coff + rg * ldc + colg;
                    __half2 h2 = __floats2half2_rn(v0, v1);
                    *(__half2*)((__half*)Cv + ci) = h2;
                    // transposed B-panel write: panel (z*8 + b), n=colg, k=i
                    long pi = (long)z * 8 + (rg >> 10);
                    char* T = (char*)R + pi * (long)DD * NN * 2;
                    int i = (int)(rg & 1023);
                    uint32_t base = (uint32_t)((colg & 127) * 64 + (i & 31) * 2);
                    long blk = ((colg >> 7) * (NN >> 5) + (i >> 5)) * 8192L;
                    *(__half*)(T + blk + pan(base))      = __low2half(h2);
                    *(__half*)(T + blk + pan(base + 64)) = __high2half(h2);
                } else {
                    long ci = coff + rg * ldc + colg;
                    float2 rv = *(const float2*)&Rb[ci - coff];
                    v0 += rv.x; v1 += rv.y;
                    float2 o; o.x = v0; o.y = v1;
                    *(float2*)((float*)Cv + ci) = o;
                }
            }
        }
    }
}

// ----------------------------------------------------------------------------
// X -> fp16 A-panel (K = 768, 128-row blocks).
// ----------------------------------------------------------------------------
__global__ void __launch_bounds__(256)
f2h_pan_kernel(const float4* __restrict__ in, char* __restrict__ out, long nu)
{
    long u = (long)blockIdx.x * 256 + threadIdx.x;
    if (u >= nu) return;
    long m = u / (DD / 8);
    int  k0 = (int)(u % (DD / 8)) * 8;
    float4 v0 = in[(m * DD + k0) >> 2];
    float4 v1 = in[((m * DD + k0) >> 2) + 1];
    __half2 h[4];
    h[0] = __floats2half2_rn(v0.x, v0.y);
    h[1] = __floats2half2_rn(v0.z, v0.w);
    h[2] = __floats2half2_rn(v1.x, v1.y);
    h[3] = __floats2half2_rn(v1.z, v1.w);
    long ba = ((m >> 7) * (DD >> 5) + (k0 >> 5)) * 8192L +
              pan((uint32_t)((m & 127) * 64 + (k0 & 31) * 2));
    *(uint4*)(out + ba) = *(uint4*)h;
}

// ----------------------------------------------------------------------------
// batched transpose+convert f32 [z][R][C] -> f16 B-panel [z] rows=C, K=R
// ----------------------------------------------------------------------------
__global__ void __launch_bounds__(256)
transpose_h_pan(const float* __restrict__ in, char* __restrict__ out, int R, int C)
{
    __shared__ float t[32][33];
    long z = blockIdx.z;
    in  += z * (long)R * C;
    char* oz = out + z * (long)R * C * 2;
    int x = blockIdx.x * 32;
    int y = blockIdx.y * 32;
    int tx = threadIdx.x & 31, ty = threadIdx.x >> 5;
    #pragma unroll
    for (int i = 0; i < 32; i += 8)
        t[ty + i][tx] = in[(long)(y + ty + i) * C + x + tx];
    __syncthreads();
    #pragma unroll
    for (int i = 0; i < 32; i += 8) {
        int n = x + ty + i;
        int k = y + tx;
        long ba = (((long)(n >> 7)) * (R >> 5) + (k >> 5)) * 8192L +
                  pan((uint32_t)((n & 127) * 64 + (k & 31) * 2));
        *(__half*)(oz + ba) = __float2half_rn(t[tx][ty + i]);
    }
}

// ----------------------------------------------------------------------------
// fast exp (FMA only)
// ----------------------------------------------------------------------------
__device__ __forceinline__ float fexp(float x) {
    float y = x * 1.4426950408889634f;
    y = fmaxf(y, -126.0f);
    float r = y + 12582912.0f;
    float fn = r - 12582912.0f;
    int   n  = (int)fn;
    float f  = y - fn;
    float p = 1.3400e-3f;
    p = fmaf(p, f, 9.6784351e-3f);
    p = fmaf(p, f, 5.5503426e-2f);
    p = fmaf(p, f, 2.4022652e-1f);
    p = fmaf(p, f, 6.9314718e-1f);
    p = fmaf(p, f, 1.0f);
    return __int_as_float(__float_as_int(p) + (n << 23));
}

// ----------------------------------------------------------------------------
// f1/f2: warp-per-(row,head) dual dot products; Wh row-major fp16
// ----------------------------------------------------------------------------
__global__ void __launch_bounds__(256)
fvec_h_kernel(const __half* __restrict__ Wh, const float* __restrict__ a,
              float* __restrict__ f1, float* __restrict__ f2, int nh)
{
    int gw = (blockIdx.x * 256 + threadIdx.x) >> 5;
    int l = threadIdx.x & 31;
    if (gw >= MM * nh) return;
    int h = gw / MM;
    const __half2* wv = (const __half2*)(Wh + (long)gw * DD);
    const float2* a1 = (const float2*)(a + (long)h * 2 * DD);
    const float2* a2 = (const float2*)(a + (long)h * 2 * DD + DD);
    float s1 = 0.0f, s2 = 0.0f;
    #pragma unroll
    for (int i = 0; i < DD / 64; i++) {
        int idx = l + i * 32;
        float2 v = __half22float2(wv[idx]);
        float2 x = a1[idx], y = a2[idx];
        s1 += v.x * x.x + v.y * x.y;
        s2 += v.x * y.x + v.y * y.y;
    }
    #pragma unroll
    for (int o = 16; o; o >>= 1) {
        s1 += __shfl_xor_sync(0xFFFFFFFFu, s1, o);
        s2 += __shfl_xor_sync(0xFFFFFFFFu, s2, o);
    }
    if (l == 0) { f1[gw] = s1; f2[gw] = s2; }
}

// ----------------------------------------------------------------------------
// masked softmax rows -> P A-panels (fp16, swizzled, 128-row blocks)
// ----------------------------------------------------------------------------
__global__ void __launch_bounds__(256)
attn_rows_kernel(const int* __restrict__ adj,
                 const float* __restrict__ f1, const float* __restrict__ f2,
                 __half* __restrict__ P, int nheads)
{
    int r = blockIdx.x;
    int b = r >> 10;
    int i = r & 1023;
    int t = threadIdx.x;
    int l = t & 31, w = t >> 5;

    __shared__ float wmax[8];
    __shared__ float wsum[8];

    int av[NN / 256];
    const int* arow = adj + (long)r * NN;
    #pragma unroll
    for (int k = 0; k < NN / 256; k++) av[k] = arow[t + k * 256];

    for (int h = 0; h < nheads; h++) {
        float f1v = f1[(long)h * MM + r];
        const float* f2h = f2 + (long)h * MM + (long)b * NN;

        float sv[NN / 256];
        float lmax = -INFINITY;
        #pragma unroll
        for (int k = 0; k < NN / 256; k++) {
            float s = f1v + f2h[t + k * 256];
            s = (s > 0.0f) ? s : ALPHA_LRELU * s;
            sv[k] = s;
            if (av[k]) lmax = fmaxf(lmax, s);
        }
        #pragma unroll
        for (int o = 16; o; o >>= 1)
            lmax = fmaxf(lmax, __shfl_xor_sync(0xFFFFFFFFu, lmax, o));
        if (l == 0) wmax[w] = lmax;
        __syncthreads();
        float m = wmax[0];
        #pragma unroll
        for (int q = 1; q < 8; q++) m = fmaxf(m, wmax[q]);

        float lsum = 0.0f;
        #pragma unroll
        for (int k = 0; k < NN / 256; k++) {
            float e = av[k] ? fexp(sv[k] - m) : 0.0f;
            sv[k] = e;
            lsum += e;
        }
        #pragma unroll
        for (int o = 16; o; o >>= 1)
            lsum += __shfl_xor_sync(0xFFFFFFFFu, lsum, o);
        if (l == 0) wsum[w] = lsum;
        __syncthreads();
        float den = 0.0f;
        #pragma unroll
        for (int q = 0; q < 8; q++) den += wsum[q];
        float rd = 1.0f / den;

        char* Pz = (char*)(P + (((long)h * BB + b) * NN) * NN);
        #pragma unroll
        for (int k = 0; k < NN / 256; k++) {
            int j = t + k * 256;
            long ba = (((long)(i >> 7)) * (NN >> 5) + (j >> 5)) * 8192L +
                      pan((uint32_t)((i & 127) * 64 + (j & 31) * 2));
            *(__half*)(Pz + ba) = __float2half_rn(sv[k] * rd);
        }
        __syncthreads();
    }
}

// ----------------------------------------------------------------------------
// classifier: warp-per-row
// ----------------------------------------------------------------------------
__global__ void __launch_bounds__(256)
classifier_kernel(const float* __restrict__ yy, const float* __restrict__ wc,
                  const float* __restrict__ bc, const float* __restrict__ mask,
                  float* __restrict__ scores)
{
    int gw = (blockIdx.x * 256 + threadIdx.x) >> 5;
    int l = threadIdx.x & 31;
    if (gw >= MM) return;
    const float4* y = (const float4*)(yy + (long)gw * DD);
    const float4* wv = (const float4*)wc;
    float s = 0.0f;
    #pragma unroll
    for (int i = 0; i < DD / 128; i++) {
        int idx = l + i * 32;
        float4 a = y[idx], b = wv[idx];
        s += a.x * b.x + a.y * b.y + a.z * b.z + a.w * b.w;
    }
    #pragma unroll
    for (int o = 16; o; o >>= 1) s += __shfl_xor_sync(0xFFFFFFFFu, s, o);
    if (l == 0) {
        float v = s + bc[0];
        scores[gw] = (1.0f / (1.0f + expf(-v))) * mask[gw];
    }
}

// ----------------------------------------------------------------------------
// launch
// ----------------------------------------------------------------------------
extern "C" void kernel_launch(void* const* d_in, const int* in_sizes, int n_in,
                              void* d_out, int out_size)
{
    const float* input_emb = (const float*)d_in[0];
    const int*   adj       = (const int*)d_in[1];
    const float* mask_node = (const float*)d_in[2];
    const float* W_heads   = (const float*)d_in[3];
    const float* a_heads   = (const float*)d_in[4];
    const float* W_out     = (const float*)d_in[5];
    const float* a_out     = (const float*)d_in[6];
    const float* w_cls     = (const float*)d_in[7];
    const float* b_cls     = (const float*)d_in[8];

    float* yy     = (float*)d_out;
    float* scores = (float*)d_out + (long)MM * DD;

    __half *p_X16, *p_W16T, *p_Wo16T, *p_Wh16, *p_WhT16, *p_xx16, *p_Who16, *p_WhoT16, *p_P16;
    float *p_f1, *p_f2, *p_f1o, *p_f2o;
    cudaGetSymbolAddress((void**)&p_X16,    g_X16);
    cudaGetSymbolAddress((void**)&p_W16T,   g_W16T);
    cudaGetSymbolAddress((void**)&p_Wo16T,  g_Wo16T);
    cudaGetSymbolAddress((void**)&p_Wh16,   g_Wh16);
    cudaGetSymbolAddress((void**)&p_WhT16,  g_WhT16);
    cudaGetSymbolAddress((void**)&p_xx16,   g_xx16);
    cudaGetSymbolAddress((void**)&p_Who16,  g_Who16);
    cudaGetSymbolAddress((void**)&p_WhoT16, g_WhoT16);
    cudaGetSymbolAddress((void**)&p_P16,    g_P16);
    cudaGetSymbolAddress((void**)&p_f1,     g_f1);
    cudaGetSymbolAddress((void**)&p_f2,     g_f2);
    cudaGetSymbolAddress((void**)&p_f1o,    g_f1o);
    cudaGetSymbolAddress((void**)&p_f2o,    g_f2o);

    cudaFuncSetAttribute(hgemm<1>, cudaFuncAttributeMaxDynamicSharedMemorySize, GEMM_SMEM);
    cudaFuncSetAttribute(hgemm<2>, cudaFuncAttributeMaxDynamicSharedMemorySize, GEMM_SMEM);
    cudaFuncSetAttribute(hgemm<5>, cudaFuncAttributeMaxDynamicSharedMemorySize, GEMM_SMEM);

    const int ZBIG = 1 << 30;

    // 0) producers: X -> A-panel; W_heads/W_out -> B-panels
    {
        long nu = (long)MM * DD / 8;
        f2h_pan_kernel<<<(unsigned)((nu + 255) / 256), 256>>>(
            (const float4*)input_emb, (char*)p_X16, nu);
    }
    transpose_h_pan<<<dim3(DD / 32, DD / 32, HH), 256>>>(W_heads, (char*)p_W16T, DD, DD);
    transpose_h_pan<<<dim3(DD / 32, (HH * DD) / 32, 1), 256>>>(W_out, (char*)p_Wo16T, HH * DD, DD);

    // 1) Wh[h] = X @ W_heads[h] -> fp16 row-major + WhT B-panels (fused)
    hgemm<5><<<dim3(DD / 128, MM / 128, HH), 256, GEMM_SMEM>>>(
        p_X16, p_W16T, p_Wh16, (const float*)p_WhT16, DD, DD,
        0L, (long)DD * DD, (long)MM * DD, 0L, ZBIG, 0L);

    // 2) f1/f2
    fvec_h_kernel<<<(MM * HH * 32 + 255) / 256, 256>>>(p_Wh16, a_heads, p_f1, p_f2, HH);

    // 3) attention probs -> P A-panels
    attn_rows_kernel<<<MM, 256>>>(adj, p_f1, p_f2, p_P16, HH);

    // 4) xx = elu(P @ Wh) -> A-panel (K=3072)
    hgemm<1><<<dim3(DD / 128, NN / 128, HH * BB), 256, GEMM_SMEM>>>(
        p_P16, p_WhT16, p_xx16, nullptr, NN, HH * DD,
        (long)NN * NN, (long)DD * NN,
        (long)NN, (long)DD, BB, 0L);

    // 5) Who = xx @ W_out -> fp16 row-major + WhoT B-panels (fused, K=3072)
    hgemm<5><<<dim3(DD / 128, MM / 128, 1), 256, GEMM_SMEM>>>(
        p_xx16, p_Wo16T, p_Who16, (const float*)p_WhoT16, HH * DD, DD,
        0L, 0L, 0L, 0L, ZBIG, 0L);

    // 6) f1o/f2o
    fvec_h_kernel<<<(MM * 32 + 255) / 256, 256>>>(p_Who16, a_out, p_f1o, p_f2o, 1);

    // 7) out-layer attention probs -> P A-panels (h=0 blocks)
    attn_rows_kernel<<<MM, 256>>>(adj, p_f1o, p_f2o, p_P16, 1);

    // 8) yy = elu(P @ Who) + input_emb -> f32 row-major
    hgemm<2><<<dim3(DD / 128, NN / 128, BB), 256, GEMM_SMEM>>>(
        p_P16, p_WhoT16, yy, input_emb, NN, DD,
        (long)NN * NN, (long)DD * NN,
        (long)NN * DD, 0L, ZBIG, (long)NN * DD);

    // 9) classifier
    classifier_kernel<<<(MM * 32 + 255) / 256, 256>>>(yy, w_cls, b_cls, mask_node, scores);

    (void)in_sizes; (void)n_in; (void)out_size;
}

// round 16
// speedup vs baseline: 1.5301x; 1.5301x over previous
#include <cuda_runtime.h>
#include <cuda_fp16.h>
#include <math.h>
#include <stdint.h>

// Problem constants
#define BB 8
#define NN 1024
#define DD 768
#define HH 4
#define MM (BB * NN)
#define ALPHA_LRELU 0.2f

// ----------------------------------------------------------------------------
// Scratch. GEMM operands live as SWIZZLED PANELS:
//   panel block: [blk128][kchunk][128 rows x 32 halves] = 8KB
//   in-block byte addr = pan(row*64 + (k%32)*2), pan(x) = x ^ ((x>>3)&0x30)
// ----------------------------------------------------------------------------
__device__ __align__(256) __half g_X16[(long)MM * DD];              // A-panel K=768
__device__ __align__(256) __half g_W16T[(long)HH * DD * DD];        // B-panel K=768 per head
__device__ __align__(256) __half g_Wo16T[(long)DD * HH * DD];       // B-panel K=3072
__device__ __align__(256) __half g_Wh16[(long)HH * MM * DD];        // row-major (fvec)
__device__ __align__(256) __half g_WhT16[(long)HH * BB * DD * NN];  // B-panel K=1024 per (h,b)
__device__ __align__(256) __half g_xx16[(long)MM * (HH * DD)];      // A-panel K=3072
__device__ __align__(256) __half g_Who16[(long)MM * DD];            // row-major (fvec)
__device__ __align__(256) __half g_WhoT16[(long)BB * DD * NN];      // B-panel K=1024 per b
__device__ __align__(256) __half g_P16[(long)HH * BB * NN * NN];    // A-panel K=1024 per (h,b)
__device__ float g_f1[HH * MM];
__device__ float g_f2[HH * MM];
__device__ float g_f1o[MM];
__device__ float g_f2o[MM];

// ----------------------------------------------------------------------------
// helpers
// ----------------------------------------------------------------------------
__device__ __forceinline__ uint32_t smem_u32(const void* p) {
    uint32_t a;
    asm("{ .reg .u64 t; cvta.to.shared.u64 t, %1; cvt.u32.u64 %0, t; }" : "=r"(a) : "l"(p));
    return a;
}
__device__ __host__ __forceinline__ uint32_t pan(uint32_t x) {
    return x ^ ((x >> 3) & 0x30);
}
__device__ __forceinline__ void ldsm_x4(uint32_t& r0, uint32_t& r1, uint32_t& r2, uint32_t& r3,
                                        uint32_t addr) {
    asm volatile("ldmatrix.sync.aligned.m8n8.x4.shared.b16 {%0,%1,%2,%3}, [%4];"
                 : "=r"(r0), "=r"(r1), "=r"(r2), "=r"(r3) : "r"(addr));
}

#define MBAR_INIT(addr, cnt) \
    asm volatile("mbarrier.init.shared.b64 [%0], %1;" :: "r"(addr), "r"(cnt) : "memory")
#define MBAR_EXPECT(addr, bytes) \
    asm volatile("mbarrier.arrive.expect_tx.shared.b64 _, [%0], %1;" :: "r"(addr), "r"(bytes) : "memory")
#define MBAR_ARRIVE(addr) \
    asm volatile("mbarrier.arrive.shared.b64 _, [%0];" :: "r"(addr) : "memory")
#define MBAR_WAIT(addr, par) do { \
    asm volatile("{\n\t.reg .pred P1;\n\tWL_%=:\n\t" \
        "mbarrier.try_wait.parity.shared.b64 P1, [%0], %1;\n\t" \
        "@P1 bra.uni WD_%=;\n\tbra.uni WL_%=;\n\tWD_%=:\n\t}" \
        :: "r"(addr), "r"(par) : "memory"); \
} while (0)
#define BULK_G2S(dst, src, bytes, mbar) \
    asm volatile("cp.async.bulk.shared::cluster.global.mbarrier::complete_tx::bytes [%0], [%1], %2, [%3];" \
        :: "r"(dst), "l"(src), "r"(bytes), "r"(mbar) : "memory")

// ----------------------------------------------------------------------------
// fp16 mma.sync GEMM over swizzled panels.
// 128x128 CTA tile, 256 threads (8 warps, warp 32x64), KT=32, 6-stage
// cp.async.bulk pipeline, full/empty mbarriers, 2 CTAs/SM, warp start stagger.
// EPI: 1 = elu -> half A-PANEL out, 2 = elu + residual -> f32 row-major,
//      5 = plain -> half row-major AND transposed B-panel via smem staging
//          (R = transposed-panel base; coalesced 16B panel stores)
// ----------------------------------------------------------------------------
#define KT 32
#define STAGES 6
#define ABLK 8192
#define BBLK 8192
#define STAGEB (ABLK + BBLK)                  // 16384
#define GEMM_SMEM (STAGES * STAGEB + 128)     // 98432 -> 2 CTAs/SM

template <int EPI>
__global__ void __launch_bounds__(256, 2)
hgemm(const __half* __restrict__ A, const __half* __restrict__ B,
      void* __restrict__ Cv, const float* __restrict__ R,
      int K, int ldc, long sA, long sB, long sC, long sC2, int zmod, long sR)
{
    extern __shared__ char smc[];
    uint32_t sb = smem_u32(smc);
    uint32_t fullb = sb + STAGES * STAGEB;
    uint32_t emptyb = fullb + 64;
    int tid = threadIdx.x;
    int l = tid & 31;
    int w = tid >> 5;

    int z = blockIdx.z;
    const char* Ag = (const char*)(A + (long)z * sA);
    const char* Bg = (const char*)(B + (long)z * sB);
    const float* Rb = (EPI == 2) ? (R + (long)z * sR) : nullptr;

    int brow = blockIdx.y * 128;
    int bcol = blockIdx.x * 128;
    int m0 = (w & 3) * 32;
    int n0 = (w >> 2) * 64;

    float c[2][8][4];
    #pragma unroll
    for (int i = 0; i < 2; i++)
        #pragma unroll
        for (int j = 0; j < 8; j++)
            #pragma unroll
            for (int q = 0; q < 4; q++) c[i][j][q] = 0.0f;

    int nk = K / KT;

    if (tid == 0) {
        #pragma unroll
        for (int b = 0; b < STAGES; b++) {
            MBAR_INIT(fullb + b * 8, 1);
            MBAR_INIT(emptyb + b * 8, 8);
        }
    }
    __syncthreads();

    auto issue = [&](int s) {
        int buf = s % STAGES;
        MBAR_WAIT(emptyb + buf * 8, (uint32_t)(((s / STAGES) + 1) & 1));
        uint32_t dst = sb + buf * STAGEB;
        uint32_t bar = fullb + buf * 8;
        const char* srcA = Ag + ((long)blockIdx.y * (K >> 5) + s) * ABLK;
        const char* srcB = Bg + ((long)blockIdx.x * (K >> 5) + s) * BBLK;
        asm volatile("fence.proxy.async.shared::cta;" ::: "memory");
        MBAR_EXPECT(bar, STAGEB);
        BULK_G2S(dst, srcA, ABLK, bar);
        BULK_G2S(dst + ABLK, srcB, BBLK, bar);
    };

    if (tid == 0) {
        for (int pf = 0; pf < STAGES - 1 && pf < nk; pf++) issue(pf);
    }

    // per-warp start stagger (~48*w cycles)
    {
        float dly = 1.0f + (float)l * 1e-30f;
        int iters = w * 12;
        for (int i = 0; i < iters; i++)
            dly = fmaf(dly, 1.0000001f, 1e-30f);
        if (dly == 1234.5f) ((volatile float*)Cv)[0] = dly;   // never true
    }

    uint32_t aof[2][2], bof[4][2];
    #pragma unroll
    for (int mi = 0; mi < 2; mi++)
        #pragma unroll
        for (int ks = 0; ks < 2; ks++)
            aof[mi][ks] = pan((uint32_t)(m0 + mi * 16 + (l & 15)) * 64 +
                              (uint32_t)ks * 32 + (uint32_t)(l >> 4) * 16);
    #pragma unroll
    for (int np = 0; np < 4; np++)
        #pragma unroll
        for (int ks = 0; ks < 2; ks++)
            bof[np][ks] = pan((uint32_t)(n0 + np * 16 + (l & 15)) * 64 +
                              (uint32_t)ks * 32 + (uint32_t)(l >> 4) * 16);

    for (int s = 0; s < nk; s++) {
        int buf = s % STAGES;
        MBAR_WAIT(fullb + buf * 8, (uint32_t)((s / STAGES) & 1));

        uint32_t tA = sb + buf * STAGEB;
        uint32_t tB = tA + ABLK;

        // ks = 0
        {
            uint32_t a[2][4], b[4][4];
            #pragma unroll
            for (int mi = 0; mi < 2; mi++)
                ldsm_x4(a[mi][0], a[mi][1], a[mi][2], a[mi][3], tA + aof[mi][0]);
            #pragma unroll
            for (int np = 0; np < 4; np++)
                ldsm_x4(b[np][0], b[np][1], b[np][2], b[np][3], tB + bof[np][0]);
            #pragma unroll
            for (int mi = 0; mi < 2; mi++)
                #pragma unroll
                for (int nf = 0; nf < 8; nf++) {
                    uint32_t b0 = b[nf >> 1][(nf & 1) + 0];
                    uint32_t b1 = b[nf >> 1][(nf & 1) + 2];
                    asm volatile(
                        "mma.sync.aligned.m16n8k16.row.col.f32.f16.f16.f32 "
                        "{%0,%1,%2,%3}, {%4,%5,%6,%7}, {%8,%9}, {%0,%1,%2,%3};"
                        : "+f"(c[mi][nf][0]), "+f"(c[mi][nf][1]),
                          "+f"(c[mi][nf][2]), "+f"(c[mi][nf][3])
                        : "r"(a[mi][0]), "r"(a[mi][1]), "r"(a[mi][2]), "r"(a[mi][3]),
                          "r"(b0), "r"(b1));
                }
        }
        // ks = 1
        {
            uint32_t a[2][4], b[4][4];
            #pragma unroll
            for (int mi = 0; mi < 2; mi++)
                ldsm_x4(a[mi][0], a[mi][1], a[mi][2], a[mi][3], tA + aof[mi][1]);
            #pragma unroll
            for (int np = 0; np < 4; np++)
                ldsm_x4(b[np][0], b[np][1], b[np][2], b[np][3], tB + bof[np][1]);
            if (l == 0) MBAR_ARRIVE(emptyb + buf * 8);
            if (tid == 0 && s + STAGES - 1 < nk) issue(s + STAGES - 1);
            #pragma unroll
            for (int mi = 0; mi < 2; mi++)
                #pragma unroll
                for (int nf = 0; nf < 8; nf++) {
                    uint32_t b0 = b[nf >> 1][(nf & 1) + 0];
                    uint32_t b1 = b[nf >> 1][(nf & 1) + 2];
                    asm volatile(
                        "mma.sync.aligned.m16n8k16.row.col.f32.f16.f16.f32 "
                        "{%0,%1,%2,%3}, {%4,%5,%6,%7}, {%8,%9}, {%0,%1,%2,%3};"
                        : "+f"(c[mi][nf][0]), "+f"(c[mi][nf][1]),
                          "+f"(c[mi][nf][2]), "+f"(c[mi][nf][3])
                        : "r"(a[mi][0]), "r"(a[mi][1]), "r"(a[mi][2]), "r"(a[mi][3]),
                          "r"(b0), "r"(b1));
                }
        }
    }

    long coff = (long)(z % zmod) * sC + (long)(z / zmod) * sC2;

    if (EPI == 5) {
        // row-major store + smem-staged transposed panel store
        __syncthreads();                       // reclaim pipeline smem
        __half* st = (__half*)smc;             // [128 cols][136 rows] halves
        #pragma unroll
        for (int mi = 0; mi < 2; mi++) {
            #pragma unroll
            for (int hh = 0; hh < 2; hh++) {
                int rl = m0 + mi * 16 + (l >> 2) + hh * 8;
                long rg = brow + rl;
                #pragma unroll
                for (int nf = 0; nf < 8; nf++) {
                    __half2 h2 = __floats2half2_rn(c[mi][nf][hh * 2 + 0],
                                                   c[mi][nf][hh * 2 + 1]);
                    int cl = n0 + nf * 8 + (l & 3) * 2;
                    *(__half2*)((__half*)Cv + coff + rg * ldc + bcol + cl) = h2;
                    st[(cl + 0) * 136 + rl] = __low2half(h2);
                    st[(cl + 1) * 136 + rl] = __high2half(h2);
                }
            }
        }
        __syncthreads();
        // coalesced 16B panel stores: unit = (col, rows r0..r0+7)
        long pi = (long)z * 8 + (brow >> 10);
        char* Tz = (char*)R + pi * (long)DD * NN * 2;
        int ib = brow & 1023;
        #pragma unroll
        for (int u = 0; u < 8; u++) {
            int idx = tid * 8 + u;          // 0..2047
            int cl = idx >> 4;              // local col 0..127
            int r0 = (idx & 15) * 8;        // local row start
            uint4 v = *(uint4*)&st[cl * 136 + r0];
            int n = bcol + cl;
            int i = ib + r0;
            long blk = (((long)(n >> 7)) * (NN >> 5) + (i >> 5)) * 8192L;
            uint32_t off = pan((uint32_t)((n & 127) * 64 + (i & 31) * 2));
            *(uint4*)(Tz + blk + off) = v;
        }
    } else {
        #pragma unroll
        for (int mi = 0; mi < 2; mi++) {
            #pragma unroll
            for (int hh = 0; hh < 2; hh++) {
                long rg = brow + m0 + mi * 16 + (l >> 2) + hh * 8;
                #pragma unroll
                for (int nf = 0; nf < 8; nf++) {
                    float v0 = c[mi][nf][hh * 2 + 0];
                    float v1 = c[mi][nf][hh * 2 + 1];
                    v0 = (v0 > 0.0f) ? v0 : expm1f(v0);
                    v1 = (v1 > 0.0f) ? v1 : expm1f(v1);
                    long colg = bcol + n0 + nf * 8 + (l & 3) * 2;
                    if (EPI == 1) {
                        long mg = (long)(z % zmod) * sC + rg;
                        long kg = (long)(z / zmod) * sC2 + colg;
                        long ba = ((mg >> 7) * (ldc >> 5) + (kg >> 5)) * 8192L +
                                  pan((uint32_t)((mg & 127) * 64 + (kg & 31) * 2));
                        *(__half2*)((char*)Cv + ba) = __floats2half2_rn(v0, v1);
                    } else {
                        long ci = coff + rg * ldc + colg;
                        float2 rv = *(const float2*)&Rb[ci - coff];
                        v0 += rv.x; v1 += rv.y;
                        float2 o; o.x = v0; o.y = v1;
                        *(float2*)((float*)Cv + ci) = o;
                    }
                }
            }
        }
    }
}

// ----------------------------------------------------------------------------
// X -> fp16 A-panel (K = 768, 128-row blocks).
// ----------------------------------------------------------------------------
__global__ void __launch_bounds__(256)
f2h_pan_kernel(const float4* __restrict__ in, char* __restrict__ out, long nu)
{
    long u = (long)blockIdx.x * 256 + threadIdx.x;
    if (u >= nu) return;
    long m = u / (DD / 8);
    int  k0 = (int)(u % (DD / 8)) * 8;
    float4 v0 = in[(m * DD + k0) >> 2];
    float4 v1 = in[((m * DD + k0) >> 2) + 1];
    __half2 h[4];
    h[0] = __floats2half2_rn(v0.x, v0.y);
    h[1] = __floats2half2_rn(v0.z, v0.w);
    h[2] = __floats2half2_rn(v1.x, v1.y);
    h[3] = __floats2half2_rn(v1.z, v1.w);
    long ba = ((m >> 7) * (DD >> 5) + (k0 >> 5)) * 8192L +
              pan((uint32_t)((m & 127) * 64 + (k0 & 31) * 2));
    *(uint4*)(out + ba) = *(uint4*)h;
}

// ----------------------------------------------------------------------------
// batched transpose+convert f32 [z][R][C] -> f16 B-panel [z] rows=C, K=R
// ----------------------------------------------------------------------------
__global__ void __launch_bounds__(256)
transpose_h_pan(const float* __restrict__ in, char* __restrict__ out, int R, int C)
{
    __shared__ float t[32][33];
    long z = blockIdx.z;
    in  += z * (long)R * C;
    char* oz = out + z * (long)R * C * 2;
    int x = blockIdx.x * 32;
    int y = blockIdx.y * 32;
    int tx = threadIdx.x & 31, ty = threadIdx.x >> 5;
    #pragma unroll
    for (int i = 0; i < 32; i += 8)
        t[ty + i][tx] = in[(long)(y + ty + i) * C + x + tx];
    __syncthreads();
    #pragma unroll
    for (int i = 0; i < 32; i += 8) {
        int n = x + ty + i;
        int k = y + tx;
        long ba = (((long)(n >> 7)) * (R >> 5) + (k >> 5)) * 8192L +
                  pan((uint32_t)((n & 127) * 64 + (k & 31) * 2));
        *(__half*)(oz + ba) = __float2half_rn(t[tx][ty + i]);
    }
}

// ----------------------------------------------------------------------------
// fast exp (FMA only)
// ----------------------------------------------------------------------------
__device__ __forceinline__ float fexp(float x) {
    float y = x * 1.4426950408889634f;
    y = fmaxf(y, -126.0f);
    float r = y + 12582912.0f;
    float fn = r - 12582912.0f;
    int   n  = (int)fn;
    float f  = y - fn;
    float p = 1.3400e-3f;
    p = fmaf(p, f, 9.6784351e-3f);
    p = fmaf(p, f, 5.5503426e-2f);
    p = fmaf(p, f, 2.4022652e-1f);
    p = fmaf(p, f, 6.9314718e-1f);
    p = fmaf(p, f, 1.0f);
    return __int_as_float(__float_as_int(p) + (n << 23));
}

// ----------------------------------------------------------------------------
// f1/f2: warp-per-(row,head) dual dot products; Wh row-major fp16
// ----------------------------------------------------------------------------
__global__ void __launch_bounds__(256)
fvec_h_kernel(const __half* __restrict__ Wh, const float* __restrict__ a,
              float* __restrict__ f1, float* __restrict__ f2, int nh)
{
    int gw = (blockIdx.x * 256 + threadIdx.x) >> 5;
    int l = threadIdx.x & 31;
    if (gw >= MM * nh) return;
    int h = gw / MM;
    const __half2* wv = (const __half2*)(Wh + (long)gw * DD);
    const float2* a1 = (const float2*)(a + (long)h * 2 * DD);
    const float2* a2 = (const float2*)(a + (long)h * 2 * DD + DD);
    float s1 = 0.0f, s2 = 0.0f;
    #pragma unroll
    for (int i = 0; i < DD / 64; i++) {
        int idx = l + i * 32;
        float2 v = __half22float2(wv[idx]);
        float2 x = a1[idx], y = a2[idx];
        s1 += v.x * x.x + v.y * x.y;
        s2 += v.x * y.x + v.y * y.y;
    }
    #pragma unroll
    for (int o = 16; o; o >>= 1) {
        s1 += __shfl_xor_sync(0xFFFFFFFFu, s1, o);
        s2 += __shfl_xor_sync(0xFFFFFFFFu, s2, o);
    }
    if (l == 0) { f1[gw] = s1; f2[gw] = s2; }
}

// ----------------------------------------------------------------------------
// masked softmax rows -> P A-panels (fp16, swizzled, 128-row blocks)
// ----------------------------------------------------------------------------
__global__ void __launch_bounds__(256)
attn_rows_kernel(const int* __restrict__ adj,
                 const float* __restrict__ f1, const float* __restrict__ f2,
                 __half* __restrict__ P, int nheads)
{
    int r = blockIdx.x;
    int b = r >> 10;
    int i = r & 1023;
    int t = threadIdx.x;
    int l = t & 31, w = t >> 5;

    __shared__ float wmax[8];
    __shared__ float wsum[8];

    int av[NN / 256];
    const int* arow = adj + (long)r * NN;
    #pragma unroll
    for (int k = 0; k < NN / 256; k++) av[k] = arow[t + k * 256];

    for (int h = 0; h < nheads; h++) {
        float f1v = f1[(long)h * MM + r];
        const float* f2h = f2 + (long)h * MM + (long)b * NN;

        float sv[NN / 256];
        float lmax = -INFINITY;
        #pragma unroll
        for (int k = 0; k < NN / 256; k++) {
            float s = f1v + f2h[t + k * 256];
            s = (s > 0.0f) ? s : ALPHA_LRELU * s;
            sv[k] = s;
            if (av[k]) lmax = fmaxf(lmax, s);
        }
        #pragma unroll
        for (int o = 16; o; o >>= 1)
            lmax = fmaxf(lmax, __shfl_xor_sync(0xFFFFFFFFu, lmax, o));
        if (l == 0) wmax[w] = lmax;
        __syncthreads();
        float m = wmax[0];
        #pragma unroll
        for (int q = 1; q < 8; q++) m = fmaxf(m, wmax[q]);

        float lsum = 0.0f;
        #pragma unroll
        for (int k = 0; k < NN / 256; k++) {
            float e = av[k] ? fexp(sv[k] - m) : 0.0f;
            sv[k] = e;
            lsum += e;
        }
        #pragma unroll
        for (int o = 16; o; o >>= 1)
            lsum += __shfl_xor_sync(0xFFFFFFFFu, lsum, o);
        if (l == 0) wsum[w] = lsum;
        __syncthreads();
        float den = 0.0f;
        #pragma unroll
        for (int q = 0; q < 8; q++) den += wsum[q];
        float rd = 1.0f / den;

        char* Pz = (char*)(P + (((long)h * BB + b) * NN) * NN);
        #pragma unroll
        for (int k = 0; k < NN / 256; k++) {
            int j = t + k * 256;
            long ba = (((long)(i >> 7)) * (NN >> 5) + (j >> 5)) * 8192L +
                      pan((uint32_t)((i & 127) * 64 + (j & 31) * 2));
            *(__half*)(Pz + ba) = __float2half_rn(sv[k] * rd);
        }
        __syncthreads();
    }
}

// ----------------------------------------------------------------------------
// classifier: warp-per-row
// ----------------------------------------------------------------------------
__global__ void __launch_bounds__(256)
classifier_kernel(const float* __restrict__ yy, const float* __restrict__ wc,
                  const float* __restrict__ bc, const float* __restrict__ mask,
                  float* __restrict__ scores)
{
    int gw = (blockIdx.x * 256 + threadIdx.x) >> 5;
    int l = threadIdx.x & 31;
    if (gw >= MM) return;
    const float4* y = (const float4*)(yy + (long)gw * DD);
    const float4* wv = (const float4*)wc;
    float s = 0.0f;
    #pragma unroll
    for (int i = 0; i < DD / 128; i++) {
        int idx = l + i * 32;
        float4 a = y[idx], b = wv[idx];
        s += a.x * b.x + a.y * b.y + a.z * b.z + a.w * b.w;
    }
    #pragma unroll
    for (int o = 16; o; o >>= 1) s += __shfl_xor_sync(0xFFFFFFFFu, s, o);
    if (l == 0) {
        float v = s + bc[0];
        scores[gw] = (1.0f / (1.0f + expf(-v))) * mask[gw];
    }
}

// ----------------------------------------------------------------------------
// launch
// ----------------------------------------------------------------------------
extern "C" void kernel_launch(void* const* d_in, const int* in_sizes, int n_in,
                              void* d_out, int out_size)
{
    const float* input_emb = (const float*)d_in[0];
    const int*   adj       = (const int*)d_in[1];
    const float* mask_node = (const float*)d_in[2];
    const float* W_heads   = (const float*)d_in[3];
    const float* a_heads   = (const float*)d_in[4];
    const float* W_out     = (const float*)d_in[5];
    const float* a_out     = (const float*)d_in[6];
    const float* w_cls     = (const float*)d_in[7];
    const float* b_cls     = (const float*)d_in[8];

    float* yy     = (float*)d_out;
    float* scores = (float*)d_out + (long)MM * DD;

    __half *p_X16, *p_W16T, *p_Wo16T, *p_Wh16, *p_WhT16, *p_xx16, *p_Who16, *p_WhoT16, *p_P16;
    float *p_f1, *p_f2, *p_f1o, *p_f2o;
    cudaGetSymbolAddress((void**)&p_X16,    g_X16);
    cudaGetSymbolAddress((void**)&p_W16T,   g_W16T);
    cudaGetSymbolAddress((void**)&p_Wo16T,  g_Wo16T);
    cudaGetSymbolAddress((void**)&p_Wh16,   g_Wh16);
    cudaGetSymbolAddress((void**)&p_WhT16,  g_WhT16);
    cudaGetSymbolAddress((void**)&p_xx16,   g_xx16);
    cudaGetSymbolAddress((void**)&p_Who16,  g_Who16);
    cudaGetSymbolAddress((void**)&p_WhoT16, g_WhoT16);
    cudaGetSymbolAddress((void**)&p_P16,    g_P16);
    cudaGetSymbolAddress((void**)&p_f1,     g_f1);
    cudaGetSymbolAddress((void**)&p_f2,     g_f2);
    cudaGetSymbolAddress((void**)&p_f1o,    g_f1o);
    cudaGetSymbolAddress((void**)&p_f2o,    g_f2o);

    cudaFuncSetAttribute(hgemm<1>, cudaFuncAttributeMaxDynamicSharedMemorySize, GEMM_SMEM);
    cudaFuncSetAttribute(hgemm<2>, cudaFuncAttributeMaxDynamicSharedMemorySize, GEMM_SMEM);
    cudaFuncSetAttribute(hgemm<5>, cudaFuncAttributeMaxDynamicSharedMemorySize, GEMM_SMEM);

    const int ZBIG = 1 << 30;

    // 0) producers: X -> A-panel; W_heads/W_out -> B-panels
    {
        long nu = (long)MM * DD / 8;
        f2h_pan_kernel<<<(unsigned)((nu + 255) / 256), 256>>>(
            (const float4*)input_emb, (char*)p_X16, nu);
    }
    transpose_h_pan<<<dim3(DD / 32, DD / 32, HH), 256>>>(W_heads, (char*)p_W16T, DD, DD);
    transpose_h_pan<<<dim3(DD / 32, (HH * DD) / 32, 1), 256>>>(W_out, (char*)p_Wo16T, HH * DD, DD);

    // 1) Wh[h] = X @ W_heads[h] -> fp16 row-major + WhT B-panels (fused staged)
    hgemm<5><<<dim3(DD / 128, MM / 128, HH), 256, GEMM_SMEM>>>(
        p_X16, p_W16T, p_Wh16, (const float*)p_WhT16, DD, DD,
        0L, (long)DD * DD, (long)MM * DD, 0L, ZBIG, 0L);

    // 2) f1/f2
    fvec_h_kernel<<<(MM * HH * 32 + 255) / 256, 256>>>(p_Wh16, a_heads, p_f1, p_f2, HH);

    // 3) attention probs -> P A-panels
    attn_rows_kernel<<<MM, 256>>>(adj, p_f1, p_f2, p_P16, HH);

    // 4) xx = elu(P @ Wh) -> A-panel (K=3072)
    hgemm<1><<<dim3(DD / 128, NN / 128, HH * BB), 256, GEMM_SMEM>>>(
        p_P16, p_WhT16, p_xx16, nullptr, NN, HH * DD,
        (long)NN * NN, (long)DD * NN,
        (long)NN, (long)DD, BB, 0L);

    // 5) Who = xx @ W_out -> fp16 row-major + WhoT B-panels (fused staged)
    hgemm<5><<<dim3(DD / 128, MM / 128, 1), 256, GEMM_SMEM>>>(
        p_xx16, p_Wo16T, p_Who16, (const float*)p_WhoT16, HH * DD, DD,
        0L, 0L, 0L, 0L, ZBIG, 0L);

    // 6) f1o/f2o
    fvec_h_kernel<<<(MM * 32 + 255) / 256, 256>>>(p_Who16, a_out, p_f1o, p_f2o, 1);

    // 7) out-layer attention probs -> P A-panels (h=0 blocks)
    attn_rows_kernel<<<MM, 256>>>(adj, p_f1o, p_f2o, p_P16, 1);

    // 8) yy = elu(P @ Who) + input_emb -> f32 row-major
    hgemm<2><<<dim3(DD / 128, NN / 128, BB), 256, GEMM_SMEM>>>(
        p_P16, p_WhoT16, yy, input_emb, NN, DD,
        (long)NN * NN, (long)DD * NN,
        (long)NN * DD, 0L, ZBIG, (long)NN * DD);

    // 9) classifier
    classifier_kernel<<<(MM * 32 + 255) / 256, 256>>>(yy, w_cls, b_cls, mask_node, scores);

    (void)in_sizes; (void)n_in; (void)out_size;
}

// round 17
// speedup vs baseline: 1.6360x; 1.0692x over previous
#include <cuda_runtime.h>
#include <cuda_fp16.h>
#include <math.h>
#include <stdint.h>

// Problem constants
#define BB 8
#define NN 1024
#define DD 768
#define HH 4
#define MM (BB * NN)
#define ALPHA_LRELU 0.2f

// ----------------------------------------------------------------------------
// Scratch. GEMM operands live as SWIZZLED PANELS:
//   panel block: [blk128][kchunk32][128 rows x 32 halves] = 8KB
//   in-block byte addr = pan(row*64 + (k%32)*2), pan(x) = x ^ ((x>>3)&0x30)
// ----------------------------------------------------------------------------
__device__ __align__(256) __half g_X16[(long)MM * DD];              // A-panel K=768
__device__ __align__(256) __half g_W16T[(long)HH * DD * DD];        // B-panel K=768 per head
__device__ __align__(256) __half g_Wo16T[(long)DD * HH * DD];       // B-panel K=3072
__device__ __align__(256) __half g_Wh16[(long)HH * MM * DD];        // row-major (fvec)
__device__ __align__(256) __half g_WhT16[(long)HH * BB * DD * NN];  // B-panel K=1024 per (h,b)
__device__ __align__(256) __half g_xx16[(long)MM * (HH * DD)];      // A-panel K=3072
__device__ __align__(256) __half g_Who16[(long)MM * DD];            // row-major (fvec)
__device__ __align__(256) __half g_WhoT16[(long)BB * DD * NN];      // B-panel K=1024 per b
__device__ __align__(256) __half g_P16[(long)HH * BB * NN * NN];    // A-panel K=1024 per (h,b)
__device__ float g_f1[HH * MM];
__device__ float g_f2[HH * MM];
__device__ float g_f1o[MM];
__device__ float g_f2o[MM];

// ----------------------------------------------------------------------------
// helpers
// ----------------------------------------------------------------------------
__device__ __forceinline__ uint32_t smem_u32(const void* p) {
    uint32_t a;
    asm("{ .reg .u64 t; cvta.to.shared.u64 t, %1; cvt.u32.u64 %0, t; }" : "=r"(a) : "l"(p));
    return a;
}
__device__ __host__ __forceinline__ uint32_t pan(uint32_t x) {
    return x ^ ((x >> 3) & 0x30);
}
__device__ __forceinline__ void ldsm_x4(uint32_t& r0, uint32_t& r1, uint32_t& r2, uint32_t& r3,
                                        uint32_t addr) {
    asm volatile("ldmatrix.sync.aligned.m8n8.x4.shared.b16 {%0,%1,%2,%3}, [%4];"
                 : "=r"(r0), "=r"(r1), "=r"(r2), "=r"(r3) : "r"(addr));
}

#define MBAR_INIT(addr, cnt) \
    asm volatile("mbarrier.init.shared.b64 [%0], %1;" :: "r"(addr), "r"(cnt) : "memory")
#define MBAR_EXPECT(addr, bytes) \
    asm volatile("mbarrier.arrive.expect_tx.shared.b64 _, [%0], %1;" :: "r"(addr), "r"(bytes) : "memory")
#define MBAR_ARRIVE(addr) \
    asm volatile("mbarrier.arrive.shared.b64 _, [%0];" :: "r"(addr) : "memory")
#define MBAR_WAIT(addr, par) do { \
    asm volatile("{\n\t.reg .pred P1;\n\tWL_%=:\n\t" \
        "mbarrier.try_wait.parity.shared.b64 P1, [%0], %1;\n\t" \
        "@P1 bra.uni WD_%=;\n\tbra.uni WL_%=;\n\tWD_%=:\n\t}" \
        :: "r"(addr), "r"(par) : "memory"); \
} while (0)
#define BULK_G2S(dst, src, bytes, mbar) \
    asm volatile("cp.async.bulk.shared::cluster.global.mbarrier::complete_tx::bytes [%0], [%1], %2, [%3];" \
        :: "r"(dst), "l"(src), "r"(bytes), "r"(mbar) : "memory")

// ----------------------------------------------------------------------------
// fp16 mma.sync GEMM over swizzled panels.
// 128x128 CTA tile, 256 threads (8 warps, warp 32x64), KT=64 (two 8KB panel
// blocks per stage per operand), 3-stage cp.async.bulk pipeline with
// full/empty mbarriers, 2 CTAs/SM, warp start stagger. Fewer sync points per
// K; 128-HMMA-per-warp bursts per chunk.
// EPI: 1 = elu -> half A-PANEL out, 2 = elu + residual -> f32 row-major,
//      5 = plain -> half row-major AND transposed B-panel via smem staging
// ----------------------------------------------------------------------------
#define KT 64
#define STAGES 3
#define ABLK 16384
#define BBLK 16384
#define STAGEB (ABLK + BBLK)                  // 32768
#define GEMM_SMEM (STAGES * STAGEB + 128)     // 98432 -> 2 CTAs/SM

template <int EPI>
__global__ void __launch_bounds__(256, 2)
hgemm(const __half* __restrict__ A, const __half* __restrict__ B,
      void* __restrict__ Cv, const float* __restrict__ R,
      int K, int ldc, long sA, long sB, long sC, long sC2, int zmod, long sR)
{
    extern __shared__ char smc[];
    uint32_t sb = smem_u32(smc);
    uint32_t fullb = sb + STAGES * STAGEB;
    uint32_t emptyb = fullb + 64;
    int tid = threadIdx.x;
    int l = tid & 31;
    int w = tid >> 5;

    int z = blockIdx.z;
    const char* Ag = (const char*)(A + (long)z * sA);
    const char* Bg = (const char*)(B + (long)z * sB);
    const float* Rb = (EPI == 2) ? (R + (long)z * sR) : nullptr;

    int brow = blockIdx.y * 128;
    int bcol = blockIdx.x * 128;
    int m0 = (w & 3) * 32;
    int n0 = (w >> 2) * 64;

    float c[2][8][4];
    #pragma unroll
    for (int i = 0; i < 2; i++)
        #pragma unroll
        for (int j = 0; j < 8; j++)
            #pragma unroll
            for (int q = 0; q < 4; q++) c[i][j][q] = 0.0f;

    int nk = K / KT;                       // chunks of 64

    if (tid == 0) {
        #pragma unroll
        for (int b = 0; b < STAGES; b++) {
            MBAR_INIT(fullb + b * 8, 1);
            MBAR_INIT(emptyb + b * 8, 8);
        }
    }
    __syncthreads();

    auto issue = [&](int s) {
        int buf = s % STAGES;
        MBAR_WAIT(emptyb + buf * 8, (uint32_t)(((s / STAGES) + 1) & 1));
        uint32_t dst = sb + buf * STAGEB;
        uint32_t bar = fullb + buf * 8;
        const char* srcA = Ag + ((long)blockIdx.y * (K >> 5) + s * 2) * 8192L;
        const char* srcB = Bg + ((long)blockIdx.x * (K >> 5) + s * 2) * 8192L;
        asm volatile("fence.proxy.async.shared::cta;" ::: "memory");
        MBAR_EXPECT(bar, STAGEB);
        BULK_G2S(dst, srcA, ABLK, bar);
        BULK_G2S(dst + ABLK, srcB, BBLK, bar);
    };

    if (tid == 0) {
        for (int pf = 0; pf < STAGES - 1 && pf < nk; pf++) issue(pf);
    }

    // per-warp start stagger (~48*w cycles)
    {
        float dly = 1.0f + (float)l * 1e-30f;
        int iters = w * 12;
        for (int i = 0; i < iters; i++)
            dly = fmaf(dly, 1.0000001f, 1e-30f);
        if (dly == 1234.5f) ((volatile float*)Cv)[0] = dly;   // never true
    }

    // LDSM lane offsets within an 8KB panel block (indexed by ks&1)
    uint32_t aof[2][2], bof[4][2];
    #pragma unroll
    for (int mi = 0; mi < 2; mi++)
        #pragma unroll
        for (int kh = 0; kh < 2; kh++)
            aof[mi][kh] = pan((uint32_t)(m0 + mi * 16 + (l & 15)) * 64 +
                              (uint32_t)kh * 32 + (uint32_t)(l >> 4) * 16);
    #pragma unroll
    for (int np = 0; np < 4; np++)
        #pragma unroll
        for (int kh = 0; kh < 2; kh++)
            bof[np][kh] = pan((uint32_t)(n0 + np * 16 + (l & 15)) * 64 +
                              (uint32_t)kh * 32 + (uint32_t)(l >> 4) * 16);

    for (int s = 0; s < nk; s++) {
        int buf = s % STAGES;
        MBAR_WAIT(fullb + buf * 8, (uint32_t)((s / STAGES) & 1));

        uint32_t tA = sb + buf * STAGEB;
        uint32_t tBb = tA + ABLK;

        #pragma unroll
        for (int ks = 0; ks < 4; ks++) {
            uint32_t sub = (uint32_t)(ks >> 1) * 8192u;
            uint32_t a[2][4], b[4][4];
            #pragma unroll
            for (int mi = 0; mi < 2; mi++)
                ldsm_x4(a[mi][0], a[mi][1], a[mi][2], a[mi][3],
                        tA + sub + aof[mi][ks & 1]);
            #pragma unroll
            for (int np = 0; np < 4; np++)
                ldsm_x4(b[np][0], b[np][1], b[np][2], b[np][3],
                        tBb + sub + bof[np][ks & 1]);
            if (ks == 3) {
                if (l == 0) MBAR_ARRIVE(emptyb + buf * 8);
                if (tid == 0 && s + STAGES - 1 < nk) issue(s + STAGES - 1);
            }
            #pragma unroll
            for (int mi = 0; mi < 2; mi++)
                #pragma unroll
                for (int nf = 0; nf < 8; nf++) {
                    uint32_t b0 = b[nf >> 1][(nf & 1) + 0];
                    uint32_t b1 = b[nf >> 1][(nf & 1) + 2];
                    asm volatile(
                        "mma.sync.aligned.m16n8k16.row.col.f32.f16.f16.f32 "
                        "{%0,%1,%2,%3}, {%4,%5,%6,%7}, {%8,%9}, {%0,%1,%2,%3};"
                        : "+f"(c[mi][nf][0]), "+f"(c[mi][nf][1]),
                          "+f"(c[mi][nf][2]), "+f"(c[mi][nf][3])
                        : "r"(a[mi][0]), "r"(a[mi][1]), "r"(a[mi][2]), "r"(a[mi][3]),
                          "r"(b0), "r"(b1));
                }
        }
    }

    long coff = (long)(z % zmod) * sC + (long)(z / zmod) * sC2;

    if (EPI == 5) {
        // row-major store + smem-staged transposed panel store
        __syncthreads();                       // reclaim pipeline smem
        __half* st = (__half*)smc;             // [128 cols][136 rows]
        #pragma unroll
        for (int mi = 0; mi < 2; mi++) {
            #pragma unroll
            for (int hh = 0; hh < 2; hh++) {
                int rl = m0 + mi * 16 + (l >> 2) + hh * 8;
                long rg = brow + rl;
                #pragma unroll
                for (int nf = 0; nf < 8; nf++) {
                    __half2 h2 = __floats2half2_rn(c[mi][nf][hh * 2 + 0],
                                                   c[mi][nf][hh * 2 + 1]);
                    int cl = n0 + nf * 8 + (l & 3) * 2;
                    *(__half2*)((__half*)Cv + coff + rg * ldc + bcol + cl) = h2;
                    st[(cl + 0) * 136 + rl] = __low2half(h2);
                    st[(cl + 1) * 136 + rl] = __high2half(h2);
                }
            }
        }
        __syncthreads();
        long pi = (long)z * 8 + (brow >> 10);
        char* Tz = (char*)R + pi * (long)DD * NN * 2;
        int ib = brow & 1023;
        #pragma unroll
        for (int u = 0; u < 8; u++) {
            int idx = tid * 8 + u;
            int cl = idx >> 4;
            int r0 = (idx & 15) * 8;
            uint4 v = *(uint4*)&st[cl * 136 + r0];
            int n = bcol + cl;
            int i = ib + r0;
            long blk = (((long)(n >> 7)) * (NN >> 5) + (i >> 5)) * 8192L;
            uint32_t off = pan((uint32_t)((n & 127) * 64 + (i & 31) * 2));
            *(uint4*)(Tz + blk + off) = v;
        }
    } else {
        #pragma unroll
        for (int mi = 0; mi < 2; mi++) {
            #pragma unroll
            for (int hh = 0; hh < 2; hh++) {
                long rg = brow + m0 + mi * 16 + (l >> 2) + hh * 8;
                #pragma unroll
                for (int nf = 0; nf < 8; nf++) {
                    float v0 = c[mi][nf][hh * 2 + 0];
                    float v1 = c[mi][nf][hh * 2 + 1];
                    v0 = (v0 > 0.0f) ? v0 : expm1f(v0);
                    v1 = (v1 > 0.0f) ? v1 : expm1f(v1);
                    long colg = bcol + n0 + nf * 8 + (l & 3) * 2;
                    if (EPI == 1) {
                        long mg = (long)(z % zmod) * sC + rg;
                        long kg = (long)(z / zmod) * sC2 + colg;
                        long ba = ((mg >> 7) * (ldc >> 5) + (kg >> 5)) * 8192L +
                                  pan((uint32_t)((mg & 127) * 64 + (kg & 31) * 2));
                        *(__half2*)((char*)Cv + ba) = __floats2half2_rn(v0, v1);
                    } else {
                        long ci = coff + rg * ldc + colg;
                        float2 rv = *(const float2*)&Rb[ci - coff];
                        v0 += rv.x; v1 += rv.y;
                        float2 o; o.x = v0; o.y = v1;
                        *(float2*)((float*)Cv + ci) = o;
                    }
                }
            }
        }
    }
}

// ----------------------------------------------------------------------------
// X -> fp16 A-panel (K = 768, 128-row blocks).
// ----------------------------------------------------------------------------
__global__ void __launch_bounds__(256)
f2h_pan_kernel(const float4* __restrict__ in, char* __restrict__ out, long nu)
{
    long u = (long)blockIdx.x * 256 + threadIdx.x;
    if (u >= nu) return;
    long m = u / (DD / 8);
    int  k0 = (int)(u % (DD / 8)) * 8;
    float4 v0 = in[(m * DD + k0) >> 2];
    float4 v1 = in[((m * DD + k0) >> 2) + 1];
    __half2 h[4];
    h[0] = __floats2half2_rn(v0.x, v0.y);
    h[1] = __floats2half2_rn(v0.z, v0.w);
    h[2] = __floats2half2_rn(v1.x, v1.y);
    h[3] = __floats2half2_rn(v1.z, v1.w);
    long ba = ((m >> 7) * (DD >> 5) + (k0 >> 5)) * 8192L +
              pan((uint32_t)((m & 127) * 64 + (k0 & 31) * 2));
    *(uint4*)(out + ba) = *(uint4*)h;
}

// ----------------------------------------------------------------------------
// batched transpose+convert f32 [z][R][C] -> f16 B-panel [z] rows=C, K=R
// ----------------------------------------------------------------------------
__global__ void __launch_bounds__(256)
transpose_h_pan(const float* __restrict__ in, char* __restrict__ out, int R, int C)
{
    __shared__ float t[32][33];
    long z = blockIdx.z;
    in  += z * (long)R * C;
    char* oz = out + z * (long)R * C * 2;
    int x = blockIdx.x * 32;
    int y = blockIdx.y * 32;
    int tx = threadIdx.x & 31, ty = threadIdx.x >> 5;
    #pragma unroll
    for (int i = 0; i < 32; i += 8)
        t[ty + i][tx] = in[(long)(y + ty + i) * C + x + tx];
    __syncthreads();
    #pragma unroll
    for (int i = 0; i < 32; i += 8) {
        int n = x + ty + i;
        int k = y + tx;
        long ba = (((long)(n >> 7)) * (R >> 5) + (k >> 5)) * 8192L +
                  pan((uint32_t)((n & 127) * 64 + (k & 31) * 2));
        *(__half*)(oz + ba) = __float2half_rn(t[tx][ty + i]);
    }
}

// ----------------------------------------------------------------------------
// fast exp (FMA only)
// ----------------------------------------------------------------------------
__device__ __forceinline__ float fexp(float x) {
    float y = x * 1.4426950408889634f;
    y = fmaxf(y, -126.0f);
    float r = y + 12582912.0f;
    float fn = r - 12582912.0f;
    int   n  = (int)fn;
    float f  = y - fn;
    float p = 1.3400e-3f;
    p = fmaf(p, f, 9.6784351e-3f);
    p = fmaf(p, f, 5.5503426e-2f);
    p = fmaf(p, f, 2.4022652e-1f);
    p = fmaf(p, f, 6.9314718e-1f);
    p = fmaf(p, f, 1.0f);
    return __int_as_float(__float_as_int(p) + (n << 23));
}

// ----------------------------------------------------------------------------
// f1/f2: warp-per-(row,head) dual dot products; Wh row-major fp16
// ----------------------------------------------------------------------------
__global__ void __launch_bounds__(256)
fvec_h_kernel(const __half* __restrict__ Wh, const float* __restrict__ a,
              float* __restrict__ f1, float* __restrict__ f2, int nh)
{
    int gw = (blockIdx.x * 256 + threadIdx.x) >> 5;
    int l = threadIdx.x & 31;
    if (gw >= MM * nh) return;
    int h = gw / MM;
    const __half2* wv = (const __half2*)(Wh + (long)gw * DD);
    const float2* a1 = (const float2*)(a + (long)h * 2 * DD);
    const float2* a2 = (const float2*)(a + (long)h * 2 * DD + DD);
    float s1 = 0.0f, s2 = 0.0f;
    #pragma unroll
    for (int i = 0; i < DD / 64; i++) {
        int idx = l + i * 32;
        float2 v = __half22float2(wv[idx]);
        float2 x = a1[idx], y = a2[idx];
        s1 += v.x * x.x + v.y * x.y;
        s2 += v.x * y.x + v.y * y.y;
    }
    #pragma unroll
    for (int o = 16; o; o >>= 1) {
        s1 += __shfl_xor_sync(0xFFFFFFFFu, s1, o);
        s2 += __shfl_xor_sync(0xFFFFFFFFu, s2, o);
    }
    if (l == 0) { f1[gw] = s1; f2[gw] = s2; }
}

// ----------------------------------------------------------------------------
// masked softmax rows -> P A-panels (fp16, swizzled, 128-row blocks)
// ----------------------------------------------------------------------------
__global__ void __launch_bounds__(256)
attn_rows_kernel(const int* __restrict__ adj,
                 const float* __restrict__ f1, const float* __restrict__ f2,
                 __half* __restrict__ P, int nheads)
{
    int r = blockIdx.x;
    int b = r >> 10;
    int i = r & 1023;
    int t = threadIdx.x;
    int l = t & 31, w = t >> 5;

    __shared__ float wmax[8];
    __shared__ float wsum[8];

    int av[NN / 256];
    const int* arow = adj + (long)r * NN;
    #pragma unroll
    for (int k = 0; k < NN / 256; k++) av[k] = arow[t + k * 256];

    for (int h = 0; h < nheads; h++) {
        float f1v = f1[(long)h * MM + r];
        const float* f2h = f2 + (long)h * MM + (long)b * NN;

        float sv[NN / 256];
        float lmax = -INFINITY;
        #pragma unroll
        for (int k = 0; k < NN / 256; k++) {
            float s = f1v + f2h[t + k * 256];
            s = (s > 0.0f) ? s : ALPHA_LRELU * s;
            sv[k] = s;
            if (av[k]) lmax = fmaxf(lmax, s);
        }
        #pragma unroll
        for (int o = 16; o; o >>= 1)
            lmax = fmaxf(lmax, __shfl_xor_sync(0xFFFFFFFFu, lmax, o));
        if (l == 0) wmax[w] = lmax;
        __syncthreads();
        float m = wmax[0];
        #pragma unroll
        for (int q = 1; q < 8; q++) m = fmaxf(m, wmax[q]);

        float lsum = 0.0f;
        #pragma unroll
        for (int k = 0; k < NN / 256; k++) {
            float e = av[k] ? fexp(sv[k] - m) : 0.0f;
            sv[k] = e;
            lsum += e;
        }
        #pragma unroll
        for (int o = 16; o; o >>= 1)
            lsum += __shfl_xor_sync(0xFFFFFFFFu, lsum, o);
        if (l == 0) wsum[w] = lsum;
        __syncthreads();
        float den = 0.0f;
        #pragma unroll
        for (int q = 0; q < 8; q++) den += wsum[q];
        float rd = 1.0f / den;

        char* Pz = (char*)(P + (((long)h * BB + b) * NN) * NN);
        #pragma unroll
        for (int k = 0; k < NN / 256; k++) {
            int j = t + k * 256;
            long ba = (((long)(i >> 7)) * (NN >> 5) + (j >> 5)) * 8192L +
                      pan((uint32_t)((i & 127) * 64 + (j & 31) * 2));
            *(__half*)(Pz + ba) = __float2half_rn(sv[k] * rd);
        }
        __syncthreads();
    }
}

// ----------------------------------------------------------------------------
// classifier: warp-per-row
// ----------------------------------------------------------------------------
__global__ void __launch_bounds__(256)
classifier_kernel(const float* __restrict__ yy, const float* __restrict__ wc,
                  const float* __restrict__ bc, const float* __restrict__ mask,
                  float* __restrict__ scores)
{
    int gw = (blockIdx.x * 256 + threadIdx.x) >> 5;
    int l = threadIdx.x & 31;
    if (gw >= MM) return;
    const float4* y = (const float4*)(yy + (long)gw * DD);
    const float4* wv = (const float4*)wc;
    float s = 0.0f;
    #pragma unroll
    for (int i = 0; i < DD / 128; i++) {
        int idx = l + i * 32;
        float4 a = y[idx], b = wv[idx];
        s += a.x * b.x + a.y * b.y + a.z * b.z + a.w * b.w;
    }
    #pragma unroll
    for (int o = 16; o; o >>= 1) s += __shfl_xor_sync(0xFFFFFFFFu, s, o);
    if (l == 0) {
        float v = s + bc[0];
        scores[gw] = (1.0f / (1.0f + expf(-v))) * mask[gw];
    }
}

// ----------------------------------------------------------------------------
// launch
// ----------------------------------------------------------------------------
extern "C" void kernel_launch(void* const* d_in, const int* in_sizes, int n_in,
                              void* d_out, int out_size)
{
    const float* input_emb = (const float*)d_in[0];
    const int*   adj       = (const int*)d_in[1];
    const float* mask_node = (const float*)d_in[2];
    const float* W_heads   = (const float*)d_in[3];
    const float* a_heads   = (const float*)d_in[4];
    const float* W_out     = (const float*)d_in[5];
    const float* a_out     = (const float*)d_in[6];
    const float* w_cls     = (const float*)d_in[7];
    const float* b_cls     = (const float*)d_in[8];

    float* yy     = (float*)d_out;
    float* scores = (float*)d_out + (long)MM * DD;

    __half *p_X16, *p_W16T, *p_Wo16T, *p_Wh16, *p_WhT16, *p_xx16, *p_Who16, *p_WhoT16, *p_P16;
    float *p_f1, *p_f2, *p_f1o, *p_f2o;
    cudaGetSymbolAddress((void**)&p_X16,    g_X16);
    cudaGetSymbolAddress((void**)&p_W16T,   g_W16T);
    cudaGetSymbolAddress((void**)&p_Wo16T,  g_Wo16T);
    cudaGetSymbolAddress((void**)&p_Wh16,   g_Wh16);
    cudaGetSymbolAddress((void**)&p_WhT16,  g_WhT16);
    cudaGetSymbolAddress((void**)&p_xx16,   g_xx16);
    cudaGetSymbolAddress((void**)&p_Who16,  g_Who16);
    cudaGetSymbolAddress((void**)&p_WhoT16, g_WhoT16);
    cudaGetSymbolAddress((void**)&p_P16,    g_P16);
    cudaGetSymbolAddress((void**)&p_f1,     g_f1);
    cudaGetSymbolAddress((void**)&p_f2,     g_f2);
    cudaGetSymbolAddress((void**)&p_f1o,    g_f1o);
    cudaGetSymbolAddress((void**)&p_f2o,    g_f2o);

    cudaFuncSetAttribute(hgemm<1>, cudaFuncAttributeMaxDynamicSharedMemorySize, GEMM_SMEM);
    cudaFuncSetAttribute(hgemm<2>, cudaFuncAttributeMaxDynamicSharedMemorySize, GEMM_SMEM);
    cudaFuncSetAttribute(hgemm<5>, cudaFuncAttributeMaxDynamicSharedMemorySize, GEMM_SMEM);

    const int ZBIG = 1 << 30;

    // 0) producers: X -> A-panel; W_heads/W_out -> B-panels
    {
        long nu = (long)MM * DD / 8;
        f2h_pan_kernel<<<(unsigned)((nu + 255) / 256), 256>>>(
            (const float4*)input_emb, (char*)p_X16, nu);
    }
    transpose_h_pan<<<dim3(DD / 32, DD / 32, HH), 256>>>(W_heads, (char*)p_W16T, DD, DD);
    transpose_h_pan<<<dim3(DD / 32, (HH * DD) / 32, 1), 256>>>(W_out, (char*)p_Wo16T, HH * DD, DD);

    // 1) Wh[h] = X @ W_heads[h] -> fp16 row-major + WhT B-panels (fused staged)
    hgemm<5><<<dim3(DD / 128, MM / 128, HH), 256, GEMM_SMEM>>>(
        p_X16, p_W16T, p_Wh16, (const float*)p_WhT16, DD, DD,
        0L, (long)DD * DD, (long)MM * DD, 0L, ZBIG, 0L);

    // 2) f1/f2
    fvec_h_kernel<<<(MM * HH * 32 + 255) / 256, 256>>>(p_Wh16, a_heads, p_f1, p_f2, HH);

    // 3) attention probs -> P A-panels
    attn_rows_kernel<<<MM, 256>>>(adj, p_f1, p_f2, p_P16, HH);

    // 4) xx = elu(P @ Wh) -> A-panel (K=3072)
    hgemm<1><<<dim3(DD / 128, NN / 128, HH * BB), 256, GEMM_SMEM>>>(
        p_P16, p_WhT16, p_xx16, nullptr, NN, HH * DD,
        (long)NN * NN, (long)DD * NN,
        (long)NN, (long)DD, BB, 0L);

    // 5) Who = xx @ W_out -> fp16 row-major + WhoT B-panels (fused staged)
    hgemm<5><<<dim3(DD / 128, MM / 128, 1), 256, GEMM_SMEM>>>(
        p_xx16, p_Wo16T, p_Who16, (const float*)p_WhoT16, HH * DD, DD,
        0L, 0L, 0L, 0L, ZBIG, 0L);

    // 6) f1o/f2o
    fvec_h_kernel<<<(MM * 32 + 255) / 256, 256>>>(p_Who16, a_out, p_f1o, p_f2o, 1);

    // 7) out-layer attention probs -> P A-panels (h=0 blocks)
    attn_rows_kernel<<<MM, 256>>>(adj, p_f1o, p_f2o, p_P16, 1);

    // 8) yy = elu(P @ Who) + input_emb -> f32 row-major
    hgemm<2><<<dim3(DD / 128, NN / 128, BB), 256, GEMM_SMEM>>>(
        p_P16, p_WhoT16, yy, input_emb, NN, DD,
        (long)NN * NN, (long)DD * NN,
        (long)NN * DD, 0L, ZBIG, (long)NN * DD);

    // 9) classifier
    classifier_kernel<<<(MM * 32 + 255) / 256, 256>>>(yy, w_cls, b_cls, mask_node, scores);

    (void)in_sizes; (void)n_in; (void)out_size;
}